// round 17
// baseline (speedup 1.0000x reference)
#include <cuda_runtime.h>
#include <cuda_fp16.h>
#include <cstdint>

#define BB 16
#define TT 1024
#define HH 256
#define LL 2048
#define MQ 64
#define TCHK 64
#define NCHUNK 16
#define NTHR 512

// smem pitches (in halves)
#define QP 264
#define XP 264
#define EP 1048

// smem byte offsets
#define SO_RS4  0                      // float rs4[4][64]
#define SO_INV  1024                   // float inv[64]
#define SO_FLAG 1536
#define SO_Q    2048                   // 64*264*2 = 33792
#define SO_X    (2048 + 33792)         // 64*264*2 = 33792
#define SO_E    (2048 + 33792 + 33792) // 64*1048*2 = 134144
#define SMEM_BYTES (SO_E + MQ * EP * 2)   // 203776

__device__ __half g_Xh[(size_t)BB * TT * HH];

__device__ __forceinline__ uint32_t smem_u32(const void* p) {
    uint32_t a;
    asm("{ .reg .u64 t; cvta.to.shared.u64 t, %1; cvt.u32.u64 %0, t; }" : "=r"(a) : "l"(p));
    return a;
}
__device__ __forceinline__ void ldsm4(uint32_t a, uint32_t* r) {
    asm volatile("ldmatrix.sync.aligned.m8n8.x4.shared.b16 {%0,%1,%2,%3}, [%4];"
                 : "=r"(r[0]), "=r"(r[1]), "=r"(r[2]), "=r"(r[3]) : "r"(a));
}
__device__ __forceinline__ void ldsm4t(uint32_t a, uint32_t* r) {
    asm volatile("ldmatrix.sync.aligned.m8n8.x4.trans.shared.b16 {%0,%1,%2,%3}, [%4];"
                 : "=r"(r[0]), "=r"(r[1]), "=r"(r[2]), "=r"(r[3]) : "r"(a));
}
__device__ __forceinline__ void mma16816(float* d, const uint32_t* a, const uint32_t* b) {
    asm volatile("mma.sync.aligned.m16n8k16.row.col.f32.f16.f16.f32 "
                 "{%0,%1,%2,%3}, {%4,%5,%6,%7}, {%8,%9}, {%0,%1,%2,%3};"
                 : "+f"(d[0]), "+f"(d[1]), "+f"(d[2]), "+f"(d[3])
                 : "r"(a[0]), "r"(a[1]), "r"(a[2]), "r"(a[3]), "r"(b[0]), "r"(b[1]));
}

// ---------------- X f32 -> fp16 convert (one-time) ----------------
__global__ void __launch_bounds__(256)
xconv(const float* __restrict__ X)
{
    const size_t i = ((size_t)blockIdx.x * 256 + threadIdx.x) * 8;
    float4 a = *(const float4*)(X + i);
    float4 b = *(const float4*)(X + i + 4);
    half2 h[4] = { __floats2half2_rn(a.x, a.y), __floats2half2_rn(a.z, a.w),
                   __floats2half2_rn(b.x, b.y), __floats2half2_rn(b.z, b.w) };
    *(uint4*)(g_Xh + i) = *(uint4*)h;
}

// -- main fused kernel: 512 thr, 4Mx4N warps, Q frags + own-E frags in regs --
__global__ void __launch_bounds__(NTHR, 1)
pla_mma(const void*  __restrict__ labels_raw, // (B,L) int32/int64
        const float* __restrict__ table,      // (C+1,H)
        float* __restrict__ logits,           // (B,L,H)
        float* __restrict__ att)              // (B,L,T)
{
    extern __shared__ char sm[];
    float*  rs4 = (float*)(sm + SO_RS4);
    float*  inv = (float*)(sm + SO_INV);
    __half* Qs  = (__half*)(sm + SO_Q);
    __half* Xs  = (__half*)(sm + SO_X);
    __half* Es  = (__half*)(sm + SO_E);
    const uint32_t smb = smem_u32(sm);
    const uint32_t Qb = smb + SO_Q, Xb_s = smb + SO_X, Eb = smb + SO_E;

    const int tid = threadIdx.x, lane = tid & 31, w = tid >> 5;
    const int wm = w & 3, wn = w >> 2;       // 4(M) x 4(N)
    const int m0 = wm * 16;
    const int b = blockIdx.x >> 5, lt = blockIdx.x & 31, l0 = lt * MQ;
    const size_t bL = (size_t)b * LL;
    const __half* Xg = g_Xh + (size_t)b * TT * HH;

    // labels dtype detection (int64 LE, values < 2^31 => odd words zero)
    int* flag = (int*)(sm + SO_FLAG);
    if (tid == 0) {
        const int* li = (const int*)labels_raw;
        *flag = ((li[1] | li[3] | li[5] | li[7] | li[9] | li[11] | li[13] | li[15]) == 0);
    }
    __syncthreads();
    const bool is64 = (*flag != 0);

    // ---- gather Q (table[labels]) -> fp16 smem ----
    {
        const int q = tid >> 3, c0 = (tid & 7) * 4;
        const long long lidx = (long long)b * LL + l0 + q;
        const long long lab = is64 ? ((const long long*)labels_raw)[lidx]
                                   : (long long)((const int*)labels_raw)[lidx];
        const float* row = table + (size_t)lab * HH;
        #pragma unroll
        for (int j = 0; j < 8; j++) {
            const int col = c0 + j * 32;
            float4 v = *(const float4*)(row + col);
            *(half2*)(Qs + q * QP + col)     = __floats2half2_rn(v.x, v.y);
            *(half2*)(Qs + q * QP + col + 2) = __floats2half2_rn(v.z, v.w);
        }
    }
    __syncthreads();   // Qs visible

    // ---- hoist Q fragments: register-resident all kernel (64 regs) ----
    uint32_t Aq[64];
    {
        const uint32_t a1_0 = Qb + (uint32_t)(((m0 + (lane & 15)) * QP
                                               + ((lane >> 4) << 3)) * 2);
        #pragma unroll
        for (int k = 0; k < 16; k++) ldsm4(a1_0 + k * 32, Aq + 4 * k);
    }

    // ---- prefetch X chunk 0 (fp16): thread -> row tid>>3, 64B contiguous ----
    const int xrow = tid >> 3, xcol = (tid & 7) * 32;
    uint4 pr[4];
    #pragma unroll
    for (int p = 0; p < 4; p++)
        pr[p] = *(const uint4*)(Xg + (size_t)xrow * HH + xcol + p * 8);

    float rsum0 = 0.f, rsum1 = 0.f;
    float o[32];
    #pragma unroll
    for (int i = 0; i < 32; i++) o[i] = 0.f;

    const uint32_t b1_0 = Xb_s + (uint32_t)(((wn * 16 + (lane & 7) + ((lane >> 4) << 3)) * XP
                                             + ((lane >> 3) & 1) * 8) * 2);
    const uint32_t a2_0 = Eb + (uint32_t)(((m0 + (lane & 15)) * EP + ((lane >> 4) << 3)) * 2);
    const uint32_t b2_0 = Xb_s + (uint32_t)(((lane & 15) * XP + wn * 64 + ((lane >> 4) << 3)) * 2);

    const int r = lane >> 2, c2 = (lane & 3) * 2;

    for (int tc = 0; tc < NCHUNK; tc++) {
        // ---- store prefetched chunk -> Xs (direct uint4) ----
        #pragma unroll
        for (int p = 0; p < 4; p++)
            *(uint4*)(Xs + xrow * XP + xcol + p * 8) = pr[p];
        __syncthreads();

        // ---- MMA1: S[16q x 16t per warp] = Q * Xchunk^T (K=256), A in regs ----
        float sa0[4] = {0.f, 0.f, 0.f, 0.f};
        float sa1[4] = {0.f, 0.f, 0.f, 0.f};
        #pragma unroll
        for (int k = 0; k < 16; k++) {
            uint32_t Bv[4];
            ldsm4(b1_0 + k * 32, Bv);
            mma16816(sa0, Aq + 4 * k, Bv);
            mma16816(sa1, Aq + 4 * k, Bv + 2);
        }

        // ---- prefetch next chunk (overlaps epilogue + MMA2) ----
        if (tc + 1 < NCHUNK) {
            const __half* src = Xg + (size_t)((tc + 1) * TCHK + xrow) * HH + xcol;
            #pragma unroll
            for (int p = 0; p < 4; p++)
                pr[p] = *(const uint4*)(src + p * 8);
        }

        // ---- epilogue: e = exp(s) -> Es + row sums; keep own A2-frag in regs ----
        uint32_t myA[4];
        {
            const float e0 = __expf(sa0[0]), e1 = __expf(sa0[1]);
            const float e2 = __expf(sa0[2]), e3 = __expf(sa0[3]);
            const float f0 = __expf(sa1[0]), f1 = __expf(sa1[1]);
            const float f2 = __expf(sa1[2]), f3 = __expf(sa1[3]);
            rsum0 += e0 + e1 + f0 + f1;
            rsum1 += e2 + e3 + f2 + f3;
            // half2 packs double as this warp's MMA2 A-fragment for kst == wn
            // (C-frag {c0,c1|c2,c3} x n-halves == A-frag {a0,a1,a2,a3} identity)
            half2 p0 = __floats2half2_rn(e0, e1);   // rows r,   k 2c..2c+1
            half2 p1 = __floats2half2_rn(e2, e3);   // rows r+8, k 2c..2c+1
            half2 p2 = __floats2half2_rn(f0, f1);   // rows r,   k 2c+8..
            half2 p3 = __floats2half2_rn(f2, f3);   // rows r+8, k 2c+8..
            myA[0] = *(uint32_t*)&p0; myA[1] = *(uint32_t*)&p1;
            myA[2] = *(uint32_t*)&p2; myA[3] = *(uint32_t*)&p3;
            const int col = tc * TCHK + wn * 16 + c2;
            __half* e_lo = Es + (m0 + r) * EP + col;
            __half* e_hi = e_lo + 8 * EP;
            *(half2*)(e_lo)     = p0;
            *(half2*)(e_lo + 8) = p2;
            *(half2*)(e_hi)     = p1;
            *(half2*)(e_hi + 8) = p3;
        }
        __syncthreads();   // Es chunk visible to all warps

        // ---- MMA2: O[16q x 64h per warp] += E[16 x 64] * Xchunk slice ----
        #pragma unroll
        for (int kst = 0; kst < 4; kst++) {
            uint32_t A0[4], Bv[4][4];
            if (kst == wn) {       // own slice: A-frag already in registers
                A0[0] = myA[0]; A0[1] = myA[1]; A0[2] = myA[2]; A0[3] = myA[3];
            } else {
                ldsm4(a2_0 + tc * 128 + kst * 32, A0);
            }
            #pragma unroll
            for (int nb = 0; nb < 4; nb++)
                ldsm4t(b2_0 + kst * 16 * XP * 2 + nb * 32, Bv[nb]);
            #pragma unroll
            for (int nf = 0; nf < 8; nf++)
                mma16816(&o[nf * 4], A0, &Bv[nf >> 1][(nf & 1) * 2]);
        }
        __syncthreads();   // Xs free for next chunk
    }

    // ---- reduce row sums across quad lanes, publish, compute inverses ----
    {
        float v0 = rsum0, v1 = rsum1;
        v0 += __shfl_xor_sync(0xffffffffu, v0, 1);
        v0 += __shfl_xor_sync(0xffffffffu, v0, 2);
        v1 += __shfl_xor_sync(0xffffffffu, v1, 1);
        v1 += __shfl_xor_sync(0xffffffffu, v1, 2);
        if ((lane & 3) == 0) {
            rs4[wn * 64 + m0 + r]     = v0;
            rs4[wn * 64 + m0 + 8 + r] = v1;
        }
    }
    __syncthreads();
    if (tid < 64)
        inv[tid] = 1.0f / (rs4[tid] + rs4[64 + tid] + rs4[128 + tid] + rs4[192 + tid]);
    __syncthreads();

    // ---- write logits (scaled O fragments) ----
    {
        const int r0 = m0 + r;
        const float i0 = inv[r0], i1 = inv[r0 + 8];
        float* d0 = logits + (bL + l0 + r0) * HH;
        float* d1 = logits + (bL + l0 + r0 + 8) * HH;
        #pragma unroll
        for (int nf = 0; nf < 8; nf++) {
            const float* ov = &o[nf * 4];
            const int col = wn * 64 + nf * 8 + c2;
            *(float2*)(d0 + col) = make_float2(ov[0] * i0, ov[1] * i0);
            *(float2*)(d1 + col) = make_float2(ov[2] * i1, ov[3] * i1);
        }
    }

    // ---- write normalized attention from Es (single pass, coalesced) ----
    {
        const int rr = w * 4 + (lane >> 3);       // 16 warps x 4 rows
        const int cb = (lane & 7) * 4;
        const float iv = inv[rr];
        float* gd = att + (bL + l0 + rr) * TT;
        const __half* es = Es + rr * EP;
        #pragma unroll
        for (int j = 0; j < 32; j++) {
            const int col = cb + j * 32;
            float2 f0 = __half22float2(*(const half2*)(es + col));
            float2 f1 = __half22float2(*(const half2*)(es + col + 2));
            *(float4*)(gd + col) = make_float4(f0.x * iv, f0.y * iv, f1.x * iv, f1.y * iv);
        }
    }
}

extern "C" void kernel_launch(void* const* d_in, const int* in_sizes, int n_in,
                              void* d_out, int out_size)
{
    const float* X      = (const float*)d_in[0];
    const void*  labels = d_in[1];
    const float* table  = (const float*)d_in[2];
    float* logits = (float*)d_out;
    float* att    = logits + (size_t)BB * LL * HH;

    xconv<<<(BB * TT * HH) / (256 * 8), 256>>>(X);

    cudaFuncSetAttribute(pla_mma, cudaFuncAttributeMaxDynamicSharedMemorySize, SMEM_BYTES);
    pla_mma<<<BB * (LL / MQ), NTHR, SMEM_BYTES>>>(labels, table, logits, att);
}